// round 16
// baseline (speedup 1.0000x reference)
#include <cuda_runtime.h>
#include <cuda_bf16.h>
#include <mma.h>
#include <math.h>
#include <stdint.h>

using namespace nvcuda;
typedef __nv_bfloat16 bf16;

#define NAA 4096
#define DAA 128
#define DMM 512
#define PPP 32768
#define WIN 16
#define BAND 33

// ---------------- scratch (device globals) ----------------
__device__ float d_ad   [NAA * 512];
__device__ float d_qkvg [NAA * 512];
__device__ float d_gates[NAA * 256];
__device__ float d_q1   [NAA * DAA];
__device__ float d_part [4 * NAA * DAA];
__device__ int   d_bandp[NAA * BAND];    // stores pair_idx+1; 0 = empty (zero-init, idempotent)
__device__ float d_Bad  [512];
__device__ float d_Bg   [256];

__device__ bf16 d_cond_h[NAA * DAA],  d_cond_l[NAA * DAA];
__device__ bf16 d_qn_h  [NAA * DAA],  d_qn_l  [NAA * DAA];
__device__ bf16 d_qn2_h [NAA * DAA],  d_qn2_l [NAA * DAA];
__device__ bf16 d_at_h  [NAA * DAA],  d_at_l  [NAA * DAA];
__device__ bf16 d_hid_h [NAA * 512],  d_hid_l [NAA * 512];
__device__ bf16 d_Wqkvg_h[DAA * 512], d_Wqkvg_l[DAA * 512];
__device__ bf16 d_Wad_h  [DAA * 512], d_Wad_l  [DAA * 512];
__device__ bf16 d_Wff_h [DAA * 1024], d_Wff_l [DAA * 1024];
__device__ bf16 d_Wg_h   [DAA * 256], d_Wg_l   [DAA * 256];
__device__ bf16 d_Wcp_h  [DMM * DAA], d_Wcp_l  [DMM * DAA];
__device__ bf16 d_Wo_h   [DAA * DAA], d_Wo_l   [DAA * DAA];
__device__ bf16 d_Ws2_h  [DMM * DAA], d_Ws2_l  [DMM * DAA];

__device__ __forceinline__ void spl(float x, bf16& h, bf16& l) {
    h = __float2bfloat16_rn(x);
    l = __float2bfloat16_rn(x - __bfloat162float(h));
}

__device__ __forceinline__ void cpa16(uint32_t dst, const void* src) {
    asm volatile("cp.async.ca.shared.global [%0], [%1], 16;\n" :: "r"(dst), "l"(src));
}
__device__ __forceinline__ void cp_commit() { asm volatile("cp.async.commit_group;\n" ::); }
__device__ __forceinline__ void cp_wait0()  { asm volatile("cp.async.wait_group 0;\n" ::); }

// ---------------- single-stage whole-K GEMM body (K <= 128) ----------------
#define AS2 136
#define BS2 72
#define CS 68
#define GSM 71680

// If A32 != nullptr, the A panel is loaded from fp32 and converted in-kernel (K must be 128).
__device__ __forceinline__ void gemm_body(
    const bf16* __restrict__ Ah, const bf16* __restrict__ Al,
    const float* __restrict__ A32,
    const bf16* __restrict__ Bh, const bf16* __restrict__ Bl,
    const float* __restrict__ bias, float* __restrict__ C,
    bf16* __restrict__ Ch, bf16* __restrict__ Cl,
    int N, int K, int lda, int epi, const int* __restrict__ tok,
    const float* __restrict__ aux0, int bx, int by, int bz) {
    extern __shared__ __align__(16) char raw[];
    const uint32_t sbase = (uint32_t)__cvta_generic_to_shared(raw);

    const int tid = threadIdx.x;
    const int warp = tid >> 5;
    const int wm = warp >> 1, wn = warp & 1;
    const int row0 = by * 64, col0 = bx * 64;
    const int kof = bz * K;

    bf16* Ahs = (bf16*)raw;
    bf16* Als = (bf16*)(raw + 17408);
    bf16* Bhs = (bf16*)(raw + 34816);
    bf16* Bls = (bf16*)(raw + 53248);

    // B panel via cp.async (always)
    for (int i = tid; i < K * 8; i += 128) {
        int r = i >> 3, s = i & 7;
        const bf16* ph = Bh + (size_t)(kof + r) * N + col0 + s * 8;
        const bf16* pl = Bl + (size_t)(kof + r) * N + col0 + s * 8;
        uint32_t d = sbase + 34816 + r * (BS2 * 2) + s * 16;
        cpa16(d, ph);
        cpa16(d + 18432, pl);
    }
    if (A32) {
        // fp32 A: load + convert + STS (K == 128)
        for (int i = tid; i < 2048; i += 128) {     // 64 rows x 32 float4
            int r = i >> 5, s = i & 31;
            size_t arow = tok ? (size_t)tok[row0 + r] : (size_t)(row0 + r);
            float4 v = *(const float4*)(A32 + arow * lda + kof + s * 4);
            __nv_bfloat162 hh[2], ll[2];
            spl(v.x, hh[0].x, ll[0].x); spl(v.y, hh[0].y, ll[0].y);
            spl(v.z, hh[1].x, ll[1].x); spl(v.w, hh[1].y, ll[1].y);
            *(uint2*)&Ahs[r * AS2 + s * 4] = *(uint2*)hh;
            *(uint2*)&Als[r * AS2 + s * 4] = *(uint2*)ll;
        }
    } else {
        const int sh = (K == 128) ? 4 : 3;
        const int segsA = 1 << sh;
        for (int i = tid; i < 64 * segsA; i += 128) {
            int r = i >> sh, s = i & (segsA - 1);
            size_t arow = tok ? (size_t)tok[row0 + r] : (size_t)(row0 + r);
            const bf16* ph = Ah + arow * lda + kof + s * 8;
            const bf16* pl = Al + arow * lda + kof + s * 8;
            uint32_t d = sbase + r * (AS2 * 2) + s * 16;
            cpa16(d, ph);
            cpa16(d + 17408, pl);
        }
    }
    cp_commit();

    wmma::fragment<wmma::accumulator, 16, 16, 16, float> acc[2][2];
#pragma unroll
    for (int i = 0; i < 2; i++)
#pragma unroll
        for (int j = 0; j < 2; j++) wmma::fill_fragment(acc[i][j], 0.f);

    cp_wait0();
    __syncthreads();

    for (int kk = 0; kk < K; kk += 16) {
        wmma::fragment<wmma::matrix_a, 16, 16, 16, bf16, wmma::row_major> fah[2], fal[2];
        wmma::fragment<wmma::matrix_b, 16, 16, 16, bf16, wmma::row_major> fbh[2], fbl[2];
#pragma unroll
        for (int mi = 0; mi < 2; mi++) {
            wmma::load_matrix_sync(fah[mi], &Ahs[(wm * 32 + mi * 16) * AS2 + kk], AS2);
            wmma::load_matrix_sync(fal[mi], &Als[(wm * 32 + mi * 16) * AS2 + kk], AS2);
        }
#pragma unroll
        for (int ni = 0; ni < 2; ni++) {
            wmma::load_matrix_sync(fbh[ni], &Bhs[kk * BS2 + wn * 32 + ni * 16], BS2);
            wmma::load_matrix_sync(fbl[ni], &Bls[kk * BS2 + wn * 32 + ni * 16], BS2);
        }
#pragma unroll
        for (int mi = 0; mi < 2; mi++)
#pragma unroll
            for (int ni = 0; ni < 2; ni++) {
                wmma::mma_sync(acc[mi][ni], fah[mi], fbh[ni], acc[mi][ni]);
                wmma::mma_sync(acc[mi][ni], fah[mi], fbl[ni], acc[mi][ni]);
                wmma::mma_sync(acc[mi][ni], fal[mi], fbh[ni], acc[mi][ni]);
            }
    }

    if (epi == 0 || epi == 6) {
        float* dst = C + (epi == 6 ? (size_t)bz * NAA * N : 0);
#pragma unroll
        for (int mi = 0; mi < 2; mi++)
#pragma unroll
            for (int ni = 0; ni < 2; ni++)
                wmma::store_matrix_sync(&dst[(size_t)(row0 + wm * 32 + mi * 16) * N
                                             + col0 + wn * 32 + ni * 16],
                                        acc[mi][ni], N, wmma::mem_row_major);
        return;
    }

    __syncthreads();
    float* Ct = (float*)raw;
#pragma unroll
    for (int mi = 0; mi < 2; mi++)
#pragma unroll
        for (int ni = 0; ni < 2; ni++)
            wmma::store_matrix_sync(&Ct[(wm * 32 + mi * 16) * CS + wn * 32 + ni * 16],
                                    acc[mi][ni], CS, wmma::mem_row_major);
    __syncthreads();

    if (epi == 7) {
#pragma unroll
        for (int it = 0; it < 16; it++) {
            int item = tid + it * 128;
            int r = item >> 5, c = item & 31;
            float v1 = Ct[r * CS + c];
            float v3 = Ct[r * CS + c + 32];
            float hv = (v1 / (1.f + __expf(-v1))) * v3;
            int f = (col0 >> 1) + c;
            size_t o = (size_t)(row0 + r) * 512 + f;
            spl(hv, Ch[o], Cl[o]);
        }
        return;
    }

#pragma unroll
    for (int it = 0; it < 8; it++) {
        int r = (tid >> 4) + it * 8;
        int c4 = (tid & 15) * 4;
        int gr = row0 + r;
        float4 v4 = *(const float4*)&Ct[r * CS + c4];
        float vv[4] = {v4.x, v4.y, v4.z, v4.w};
#pragma unroll
        for (int u = 0; u < 4; u++) {
            int gc = col0 + c4 + u;
            float v = vv[u];
            if (epi == 1) v += bias[gc];
            else if (epi == 2) { v += bias[gc]; v = 1.f / (1.f + __expf(-v)); }
            else if (epi == 3) v += bias[gc] + aux0[gc];
            if (epi == 3) {
                bf16 h, l; spl(v, h, l);
                Ch[(size_t)gr * N + gc] = h;
                Cl[(size_t)gr * N + gc] = l;
            } else {
                C[(size_t)gr * N + gc] = v;
            }
        }
    }
}

__global__ __launch_bounds__(128)
void gemm_kernel(const bf16* __restrict__ Ah, const bf16* __restrict__ Al,
                 const bf16* __restrict__ Bh, const bf16* __restrict__ Bl,
                 const float* __restrict__ bias, float* __restrict__ C,
                 bf16* __restrict__ Ch, bf16* __restrict__ Cl,
                 int N, int K, int lda, int epi, const int* __restrict__ tok,
                 const float* __restrict__ aux0) {
    gemm_body(Ah, Al, nullptr, Bh, Bl, bias, C, Ch, Cl, N, K, lda, epi, tok, aux0,
              blockIdx.x, blockIdx.y, blockIdx.z);
}

// cond (512 CTAs: fp32 gathered h_cond, epi6) + gates (256 CTAs: fp32 c_atom, epi2)
__global__ __launch_bounds__(128)
void gemm_cond_gates_kernel(const float* __restrict__ h_cond,
                            const bf16* __restrict__ WcpH, const bf16* __restrict__ WcpL,
                            float* __restrict__ part, const int* __restrict__ tok,
                            const float* __restrict__ c_atom,
                            const bf16* __restrict__ WgH, const bf16* __restrict__ WgL,
                            const float* __restrict__ Bg, float* __restrict__ gates) {
    int b = blockIdx.x;
    if (b < 512) {
        gemm_body(nullptr, nullptr, h_cond, WcpH, WcpL, nullptr, part, nullptr, nullptr,
                  DAA, 128, DMM, 6, tok, nullptr, b & 1, (b >> 1) & 63, b >> 7);
    } else {
        int g = b - 512;
        gemm_body(nullptr, nullptr, c_atom, WgH, WgL, Bg, gates, nullptr, nullptr,
                  256, 128, 128, 2, nullptr, nullptr, g & 3, g >> 2, 0);
    }
}

// ---------------- combine kernels (8 elems/thread) ----------------
__global__ void combine3_kernel(const float* __restrict__ part,
                                const float* __restrict__ bias,
                                const float* __restrict__ temb,
                                bf16* __restrict__ outH, bf16* __restrict__ outL) {
    int t = blockIdx.x * blockDim.x + threadIdx.x;
#pragma unroll
    for (int rep = 0; rep < 2; rep++) {
        int idx = (t * 2 + rep) * 4;
        float4 v = *(const float4*)&part[idx];
        float4 p1 = *(const float4*)&part[(size_t)NAA * DAA + idx];
        float4 p2 = *(const float4*)&part[(size_t)2 * NAA * DAA + idx];
        float4 p3 = *(const float4*)&part[(size_t)3 * NAA * DAA + idx];
        int c = idx & 127;
        float4 b = *(const float4*)&bias[c];
        float4 e = *(const float4*)&temb[c];
        float vv[4] = {v.x + p1.x + p2.x + p3.x + b.x + e.x,
                       v.y + p1.y + p2.y + p3.y + b.y + e.y,
                       v.z + p1.z + p2.z + p3.z + b.z + e.z,
                       v.w + p1.w + p2.w + p3.w + b.w + e.w};
        __nv_bfloat162 h2[2], l2[2];
        spl(vv[0], h2[0].x, l2[0].x); spl(vv[1], h2[0].y, l2[0].y);
        spl(vv[2], h2[1].x, l2[1].x); spl(vv[3], h2[1].y, l2[1].y);
        *(uint2*)&outH[idx] = *(uint2*)h2;
        *(uint2*)&outL[idx] = *(uint2*)l2;
    }
}

__global__ __launch_bounds__(256)
void combine4_ln_kernel(const float* __restrict__ part,
                        const float* __restrict__ q, const float* __restrict__ qkvg,
                        const float* __restrict__ gates, const float* __restrict__ ad,
                        float* __restrict__ q1,
                        bf16* __restrict__ oh, bf16* __restrict__ ol) {
    int row = blockIdx.x * 8 + (threadIdx.x >> 5);
    int lane = threadIdx.x & 31;
    int c0 = lane * 4;
    size_t base = (size_t)row * DAA + c0;
    float4 p0 = *(const float4*)&part[base];
    float4 p1 = *(const float4*)&part[(size_t)NAA * DAA + base];
    float4 qv = *(const float4*)&q[base];
    float4 gv = *(const float4*)&qkvg[(size_t)row * 512 + 384 + c0];
    float4 g1 = *(const float4*)&gates[(size_t)row * 256 + c0];
    float vv[4];
    {
        float pp[4] = {p0.x + p1.x, p0.y + p1.y, p0.z + p1.z, p0.w + p1.w};
        float qq[4] = {qv.x, qv.y, qv.z, qv.w};
        float gg[4] = {gv.x, gv.y, gv.z, gv.w};
        float ga[4] = {g1.x, g1.y, g1.z, g1.w};
#pragma unroll
        for (int u = 0; u < 4; u++) {
            float sg = 1.f / (1.f + __expf(-gg[u]));
            vv[u] = (qq[u] + sg * pp[u]) * (1.f + ga[u]);
        }
    }
    float4 o; o.x = vv[0]; o.y = vv[1]; o.z = vv[2]; o.w = vv[3];
    *(float4*)&q1[base] = o;

    float s = vv[0] + vv[1] + vv[2] + vv[3];
    float sq = vv[0] * vv[0] + vv[1] * vv[1] + vv[2] * vv[2] + vv[3] * vv[3];
#pragma unroll
    for (int off = 16; off; off >>= 1) {
        s  += __shfl_xor_sync(0xffffffffu, s, off);
        sq += __shfl_xor_sync(0xffffffffu, sq, off);
    }
    float m = s * (1.f / 128.f);
    float var = sq * (1.f / 128.f) - m * m;
    float rstd = rsqrtf(var + 1e-5f);
    float4 g2 = *(const float4*)&ad[(size_t)row * 512 + 256 + c0];
    float4 b2 = *(const float4*)&ad[(size_t)row * 512 + 384 + c0];
    float gg2[4] = {g2.x, g2.y, g2.z, g2.w};
    float bb2[4] = {b2.x, b2.y, b2.z, b2.w};
    __nv_bfloat162 h2[2], l2[2];
#pragma unroll
    for (int u = 0; u < 4; u++) {
        float n = (vv[u] - m) * rstd;
        float r = (1.f + gg2[u]) * n + bb2[u];
        bf16 hh, ll; spl(r, hh, ll);
        ((bf16*)h2)[u] = hh; ((bf16*)l2)[u] = ll;
    }
    *(uint2*)&oh[base] = *(uint2*)h2;
    *(uint2*)&ol[base] = *(uint2*)l2;
}

__global__ void combine5_kernel(const float* __restrict__ part,
                                const float* __restrict__ q1, const float* __restrict__ gates,
                                float* __restrict__ outF) {
    int t = blockIdx.x * blockDim.x + threadIdx.x;
#pragma unroll
    for (int rep = 0; rep < 2; rep++) {
        int idx = (t * 2 + rep) * 4;
        float4 v = *(const float4*)&part[idx];
        float4 p1 = *(const float4*)&part[(size_t)NAA * DAA + idx];
        float4 p2 = *(const float4*)&part[(size_t)2 * NAA * DAA + idx];
        float4 p3 = *(const float4*)&part[(size_t)3 * NAA * DAA + idx];
        float4 qv = *(const float4*)&q1[idx];
        int i = idx >> 7, c = idx & 127;
        float4 g2 = *(const float4*)&gates[(size_t)i * 256 + 128 + c];
        float4 o;
        o.x = qv.x + g2.x * (v.x + p1.x + p2.x + p3.x);
        o.y = qv.y + g2.y * (v.y + p1.y + p2.y + p3.y);
        o.z = qv.z + g2.z * (v.z + p1.z + p2.z + p3.z);
        o.w = qv.w + g2.w * (v.w + p1.w + p2.w + p3.w);
        *(float4*)&outF[idx] = o;
    }
}

// ---------------- prep (weights only + fused pair scatter) ----------------
__global__ void prep_kernel(const float* __restrict__ wq, const float* __restrict__ wk,
                            const float* __restrict__ wv, const float* __restrict__ wg,
                            const float* __restrict__ ad1w, const float* __restrict__ ad2w,
                            const float* __restrict__ sw1, const float* __restrict__ sw3,
                            const float* __restrict__ g1w, const float* __restrict__ g2w,
                            const float* __restrict__ cpw, const float* __restrict__ wo,
                            const float* __restrict__ sw2,
                            const float* __restrict__ ad1b, const float* __restrict__ ad2b,
                            const float* __restrict__ g1b, const float* __restrict__ g2b,
                            const int* __restrict__ p_lm_idx) {
    int idx = blockIdx.x * blockDim.x + threadIdx.x;
    if (idx < 16384) {
        int r = idx >> 7, c = idx & 127;
        size_t o = (size_t)r * 512;
        spl(wq[idx], d_Wqkvg_h[o + c],       d_Wqkvg_l[o + c]);
        spl(wk[idx], d_Wqkvg_h[o + 128 + c], d_Wqkvg_l[o + 128 + c]);
        spl(wv[idx], d_Wqkvg_h[o + 256 + c], d_Wqkvg_l[o + 256 + c]);
        spl(wg[idx], d_Wqkvg_h[o + 384 + c], d_Wqkvg_l[o + 384 + c]);
        return;
    }
    idx -= 16384;
    if (idx < 32768) {
        int r = idx >> 8, c = idx & 255;
        size_t o = (size_t)r * 512;
        spl(ad1w[idx], d_Wad_h[o + c],       d_Wad_l[o + c]);
        spl(ad2w[idx], d_Wad_h[o + 256 + c], d_Wad_l[o + 256 + c]);
        return;
    }
    idx -= 32768;
    if (idx < 65536) {
        int k = idx >> 9, f = idx & 511;
        int g = f >> 5, w = f & 31;
        size_t o = (size_t)k * 1024;
        spl(sw1[idx], d_Wff_h[o + g * 64 + w],      d_Wff_l[o + g * 64 + w]);
        spl(sw3[idx], d_Wff_h[o + g * 64 + 32 + w], d_Wff_l[o + g * 64 + 32 + w]);
        return;
    }
    idx -= 65536;
    if (idx < 16384) {
        int r = idx >> 7, c = idx & 127;
        size_t o = (size_t)r * 256;
        spl(g1w[idx], d_Wg_h[o + c],       d_Wg_l[o + c]);
        spl(g2w[idx], d_Wg_h[o + 128 + c], d_Wg_l[o + 128 + c]);
        return;
    }
    idx -= 16384;
    if (idx < 65536) { spl(cpw[idx], d_Wcp_h[idx], d_Wcp_l[idx]); return; }
    idx -= 65536;
    if (idx < 16384) { spl(wo[idx], d_Wo_h[idx], d_Wo_l[idx]); return; }
    idx -= 16384;
    if (idx < 65536) { spl(sw2[idx], d_Ws2_h[idx], d_Ws2_l[idx]); return; }
    idx -= 65536;
    if (idx < 256) { d_Bad[idx] = ad1b[idx]; d_Bad[256 + idx] = ad2b[idx]; return; }
    idx -= 256;
    if (idx < 128) { d_Bg[idx] = g1b[idx]; d_Bg[128 + idx] = g2b[idx]; return; }
    idx -= 128;
    if (idx < PPP) {
        int i = p_lm_idx[2 * idx], j = p_lm_idx[2 * idx + 1];
        int dlt = j - i;
        if (dlt >= -WIN && dlt <= WIN) atomicMax(&d_bandp[i * BAND + dlt + WIN], idx + 1);
    }
}

// ---------------- first LayerNorm + AdaLN ----------------
__global__ void ln_mod_kernel(const float* __restrict__ x, const float* __restrict__ ad,
                              const float* __restrict__ lng, const float* __restrict__ lnb,
                              bf16* __restrict__ oh, bf16* __restrict__ ol) {
    int row = blockIdx.x * 8 + (threadIdx.x >> 5);
    int lane = threadIdx.x & 31;
    const float* xr = x + (size_t)row * DAA;
    float4 v = *(const float4*)(xr + lane * 4);
    float s = v.x + v.y + v.z + v.w;
    float sq = v.x * v.x + v.y * v.y + v.z * v.z + v.w * v.w;
#pragma unroll
    for (int o = 16; o; o >>= 1) {
        s  += __shfl_xor_sync(0xffffffffu, s, o);
        sq += __shfl_xor_sync(0xffffffffu, sq, o);
    }
    float m = s * (1.f / 128.f);
    float var = sq * (1.f / 128.f) - m * m;
    float rstd = rsqrtf(var + 1e-5f);
    const float* adr = ad + (size_t)row * 512;
    float xv[4] = {v.x, v.y, v.z, v.w};
#pragma unroll
    for (int u = 0; u < 4; u++) {
        int c = lane * 4 + u;
        float n = (xv[u] - m) * rstd;
        n = n * lng[c] + lnb[c];
        float r = (1.f + adr[c]) * n + adr[128 + c];
        spl(r, oh[(size_t)row * DAA + c], ol[(size_t)row * DAA + c]);
    }
}

// ---------------- banded attention, 4 queries per CTA ----------------
#define QB 4
#define KROWS 36

__global__ __launch_bounds__(256)
void attn_kernel(const float* __restrict__ QKVG, const int* __restrict__ bp,
                 const float* __restrict__ p_lm, const float* __restrict__ pair_w,
                 const float* __restrict__ pair_b,
                 bf16* __restrict__ oh, bf16* __restrict__ ol) {
    __shared__ float Kb[KROWS][DAA];
    __shared__ float Vb[KROWS][DAA];
    __shared__ float Qv[QB][DAA];
    __shared__ float sc[QB][4][BAND];
    const int i0 = blockIdx.x * QB;
    const int tid = threadIdx.x;
    const int jlo = (i0 - WIN) > 0 ? (i0 - WIN) : 0;
    const int jhi = (i0 + QB - 1 + WIN) < (NAA - 1) ? (i0 + QB - 1 + WIN) : (NAA - 1);
    const int rows = jhi - jlo + 1;

    for (int idx = tid; idx < QB * DAA; idx += 256) {
        int qq = idx >> 7, c = idx & 127;
        Qv[qq][c] = QKVG[(size_t)(i0 + qq) * 512 + c];
    }
    for (int idx = tid; idx < rows * DAA; idx += 256) {
        int r = idx >> 7, c = idx & 127;
        const float* src = QKVG + (size_t)(jlo + r) * 512;
        Kb[r][c] = src[128 + c];
        Vb[r][c] = src[256 + c];
    }
    __syncthreads();

    for (int s = tid; s < QB * 4 * BAND; s += 256) {
        int qq = s / (4 * BAND);
        int r2 = s - qq * (4 * BAND);
        int h = r2 & 3, jj = r2 >> 2;
        int i = i0 + qq;
        int j = i - WIN + jj;
        float acc = -INFINITY;
        if (j >= 0 && j < NAA) {
            int kr = j - jlo;
            acc = 0.f;
#pragma unroll
            for (int d = 0; d < 32; d++) acc += Qv[qq][h * 32 + d] * Kb[kr][h * 32 + d];
            acc *= 0.17677669529663687f;
            int p = bp[i * BAND + jj];
            if (p > 0) {
                p -= 1;
                float bs = pair_b[h];
#pragma unroll
                for (int t = 0; t < 16; t++) bs += p_lm[p * 16 + t] * pair_w[t * 4 + h];
                acc += bs;
            }
        }
        sc[qq][h][jj] = acc;
    }
    __syncthreads();

    {
        int w = tid >> 5, lane = tid & 31;
#pragma unroll
        for (int rep = 0; rep < 2; rep++) {
            int pair = w * 2 + rep;
            int qq = pair >> 2, h = pair & 3;
            float v0 = sc[qq][h][lane];
            float v1 = (lane == 0) ? sc[qq][h][32] : -INFINITY;
            float mx = fmaxf(v0, v1);
#pragma unroll
            for (int o = 16; o; o >>= 1) mx = fmaxf(mx, __shfl_xor_sync(0xffffffffu, mx, o));
            float e0 = __expf(v0 - mx);
            float e1 = (lane == 0) ? __expf(v1 - mx) : 0.f;
            float sm = e0 + e1;
#pragma unroll
            for (int o = 16; o; o >>= 1) sm += __shfl_xor_sync(0xffffffffu, sm, o);
            float inv = 1.f / sm;
            sc[qq][h][lane] = e0 * inv;
            if (lane == 0) sc[qq][h][32] = e1 * inv;
        }
    }
    __syncthreads();

    for (int idx = tid; idx < QB * DAA; idx += 256) {
        int qq = idx >> 7, col = idx & 127;
        int h = col >> 5;
        int i = i0 + qq;
        float o = 0.f;
#pragma unroll
        for (int jj = 0; jj < BAND; jj++) {
            int j = i - WIN + jj;
            if (j >= 0 && j < NAA)
                o += sc[qq][h][jj] * Vb[j - jlo][col];
        }
        spl(o, oh[(size_t)i * DAA + col], ol[(size_t)i * DAA + col]);
    }
}

// ---------------- launch ----------------
extern "C" void kernel_launch(void* const* d_in, const int* in_sizes, int n_in,
                              void* d_out, int out_size) {
    const float* q           = (const float*)d_in[0];
    const float* c_atom      = (const float*)d_in[1];
    const float* h_cond      = (const float*)d_in[2];
    const float* p_lm        = (const float*)d_in[3];
    const float* t_emb       = (const float*)d_in[4];
    const float* cond_proj_w = (const float*)d_in[5];
    const float* cond_proj_b = (const float*)d_in[6];
    const float* adaln1_w    = (const float*)d_in[7];
    const float* adaln1_b    = (const float*)d_in[8];
    const float* adaln2_w    = (const float*)d_in[9];
    const float* adaln2_b    = (const float*)d_in[10];
    const float* ln_g        = (const float*)d_in[11];
    const float* ln_b        = (const float*)d_in[12];
    const float* wq          = (const float*)d_in[13];
    const float* wk          = (const float*)d_in[14];
    const float* wv          = (const float*)d_in[15];
    const float* wg          = (const float*)d_in[16];
    const float* wo          = (const float*)d_in[17];
    const float* pair_w      = (const float*)d_in[18];
    const float* pair_b      = (const float*)d_in[19];
    const float* gate1_w     = (const float*)d_in[20];
    const float* gate1_b     = (const float*)d_in[21];
    const float* gate2_w     = (const float*)d_in[22];
    const float* gate2_b     = (const float*)d_in[23];
    const float* sw1         = (const float*)d_in[24];
    const float* sw3         = (const float*)d_in[25];
    const float* sw2         = (const float*)d_in[26];
    const int*   p_lm_idx    = (const int*)d_in[27];
    const int*   token_idx   = (const int*)d_in[28];
    float* out = (float*)d_out;

#define SYM(T, p, s) T* p; cudaGetSymbolAddress((void**)&p, s)
    SYM(float, ad, d_ad); SYM(float, qkvg, d_qkvg); SYM(float, gates, d_gates);
    SYM(float, q1, d_q1); SYM(int, bandp, d_bandp);
    SYM(float, part, d_part);
    SYM(float, Bad, d_Bad); SYM(float, Bg, d_Bg);
    SYM(bf16, cond_h, d_cond_h); SYM(bf16, cond_l, d_cond_l);
    SYM(bf16, qn_h, d_qn_h); SYM(bf16, qn_l, d_qn_l);
    SYM(bf16, qn2_h, d_qn2_h); SYM(bf16, qn2_l, d_qn2_l);
    SYM(bf16, at_h, d_at_h); SYM(bf16, at_l, d_at_l);
    SYM(bf16, hid_h, d_hid_h); SYM(bf16, hid_l, d_hid_l);
    SYM(bf16, Wqkvg_h, d_Wqkvg_h); SYM(bf16, Wqkvg_l, d_Wqkvg_l);
    SYM(bf16, Wad_h, d_Wad_h); SYM(bf16, Wad_l, d_Wad_l);
    SYM(bf16, Wff_h, d_Wff_h); SYM(bf16, Wff_l, d_Wff_l);
    SYM(bf16, Wg_h, d_Wg_h); SYM(bf16, Wg_l, d_Wg_l);
    SYM(bf16, Wcp_h, d_Wcp_h); SYM(bf16, Wcp_l, d_Wcp_l);
    SYM(bf16, Wo_h, d_Wo_h); SYM(bf16, Wo_l, d_Wo_l);
    SYM(bf16, Ws2_h, d_Ws2_h); SYM(bf16, Ws2_l, d_Ws2_l);
#undef SYM

    cudaFuncSetAttribute(gemm_kernel, cudaFuncAttributeMaxDynamicSharedMemorySize, GSM);
    cudaFuncSetAttribute(gemm_cond_gates_kernel, cudaFuncAttributeMaxDynamicSharedMemorySize, GSM);

    // prep: weights + biases + pair scatter  (278912 + 32768)
    const int PREP_N = 278912 + PPP;
    prep_kernel<<<(PREP_N + 255) / 256, 256>>>(wq, wk, wv, wg, adaln1_w, adaln2_w,
                                               sw1, sw3, gate1_w, gate2_w,
                                               cond_proj_w, wo, sw2,
                                               adaln1_b, adaln2_b, gate1_b, gate2_b,
                                               p_lm_idx);

    // cond split-K x4 (fp32-A gathered) + gates (fp32-A) fused in one launch
    gemm_cond_gates_kernel<<<768, 128, GSM>>>(h_cond, Wcp_h, Wcp_l, part, token_idx,
                                              c_atom, Wg_h, Wg_l, Bg, gates);
    combine3_kernel<<<256, 256>>>(part, cond_proj_b, t_emb, cond_h, cond_l);
    // ad = cond @ [adaln1|adaln2] + bias
    gemm_kernel<<<dim3(8, 64), 128, GSM>>>(cond_h, cond_l, Wad_h, Wad_l, Bad,
                                           ad, nullptr, nullptr, 512, 128, 128, 1,
                                           nullptr, nullptr);
    // q_n
    ln_mod_kernel<<<512, 256>>>(q, ad, ln_g, ln_b, qn_h, qn_l);
    // QKVG
    gemm_kernel<<<dim3(8, 64), 128, GSM>>>(qn_h, qn_l, Wqkvg_h, Wqkvg_l, nullptr,
                                           qkvg, nullptr, nullptr, 512, 128, 128, 0,
                                           nullptr, nullptr);
    // attention
    attn_kernel<<<NAA / QB, 256>>>(qkvg, bandp, p_lm, pair_w, pair_b, at_h, at_l);
    // wo: split-K x2 -> combine4+LN
    gemm_kernel<<<dim3(2, 64, 2), 128, GSM>>>(at_h, at_l, Wo_h, Wo_l, nullptr,
                                              part, nullptr, nullptr, DAA, 64, DAA, 6,
                                              nullptr, nullptr);
    combine4_ln_kernel<<<512, 256>>>(part, q, qkvg, gates, ad, q1, qn2_h, qn2_l);
    // FF with fused swiglu (epi=7)
    gemm_kernel<<<dim3(16, 64), 128, GSM>>>(qn2_h, qn2_l, Wff_h, Wff_l, nullptr,
                                            nullptr, hid_h, hid_l, 1024, 128, 128, 7,
                                            nullptr, nullptr);
    // sw2: split-K x4 -> combine5
    gemm_kernel<<<dim3(2, 64, 4), 128, GSM>>>(hid_h, hid_l, Ws2_h, Ws2_l, nullptr,
                                              part, nullptr, nullptr, DAA, 128, DMM, 6,
                                              nullptr, nullptr);
    combine5_kernel<<<256, 256>>>(part, q1, gates, out);
}

// round 17
// speedup vs baseline: 1.0468x; 1.0468x over previous
#include <cuda_runtime.h>
#include <cuda_bf16.h>
#include <mma.h>
#include <math.h>
#include <stdint.h>

using namespace nvcuda;
typedef __nv_bfloat16 bf16;

#define NAA 4096
#define DAA 128
#define DMM 512
#define PPP 32768
#define WIN 16
#define BAND 33

// ---------------- scratch (device globals) ----------------
__device__ float d_ad2  [NAA * 256];     // [g2|b2] per row (bias added)
__device__ float d_qkvg [NAA * 512];
__device__ float d_gates[NAA * 256];
__device__ float d_q1   [NAA * DAA];
__device__ float d_lnq  [NAA * DAA];     // LN(q)*lng+lnb (fp32)
__device__ float d_part [4 * NAA * DAA];
__device__ int   d_bandp[NAA * BAND];    // pair_idx+1; 0 = empty (zero-init, idempotent)
__device__ float d_Bad  [512];           // packed: [0,256) interleaved g1b1, [256,512) g2|b2
__device__ float d_Bg   [256];

__device__ bf16 d_cond_h[NAA * DAA],  d_cond_l[NAA * DAA];
__device__ bf16 d_qn_h  [NAA * DAA],  d_qn_l  [NAA * DAA];
__device__ bf16 d_qn2_h [NAA * DAA],  d_qn2_l [NAA * DAA];
__device__ bf16 d_at_h  [NAA * DAA],  d_at_l  [NAA * DAA];
__device__ bf16 d_hid_h [NAA * 512],  d_hid_l [NAA * 512];
__device__ bf16 d_ca_h  [NAA * DAA],  d_ca_l  [NAA * DAA];
__device__ bf16 d_hc_h  [1024 * DMM], d_hc_l  [1024 * DMM];
__device__ bf16 d_Wqkvg_h[DAA * 512], d_Wqkvg_l[DAA * 512];
__device__ bf16 d_Wad_h  [DAA * 512], d_Wad_l  [DAA * 512];
__device__ bf16 d_Wff_h [DAA * 1024], d_Wff_l [DAA * 1024];
__device__ bf16 d_Wg_h   [DAA * 256], d_Wg_l   [DAA * 256];
__device__ bf16 d_Wcp_h  [DMM * DAA], d_Wcp_l  [DMM * DAA];
__device__ bf16 d_Wo_h   [DAA * DAA], d_Wo_l   [DAA * DAA];
__device__ bf16 d_Ws2_h  [DMM * DAA], d_Ws2_l  [DMM * DAA];

__device__ __forceinline__ void spl(float x, bf16& h, bf16& l) {
    h = __float2bfloat16_rn(x);
    l = __float2bfloat16_rn(x - __bfloat162float(h));
}

__device__ __forceinline__ void cpa16(uint32_t dst, const void* src) {
    asm volatile("cp.async.ca.shared.global [%0], [%1], 16;\n" :: "r"(dst), "l"(src));
}
__device__ __forceinline__ void cp_commit() { asm volatile("cp.async.commit_group;\n" ::); }
__device__ __forceinline__ void cp_wait0()  { asm volatile("cp.async.wait_group 0;\n" ::); }

// ---------------- single-stage whole-K GEMM body (K <= 128) ----------------
#define AS2 136
#define BS2 72
#define CS 68
#define GSM 71680

// epi: 0 raw->C, 2 sigmoid(+bias), 6 split-K partial, 7 swiglu-pack,
//      8 adaln combined: bx<4 modulation->qn hi/lo, bx>=4 +bias->ad2[256-wide]
__device__ __forceinline__ void gemm_body(
    const bf16* __restrict__ Ah, const bf16* __restrict__ Al,
    const bf16* __restrict__ Bh, const bf16* __restrict__ Bl,
    const float* __restrict__ bias, float* __restrict__ C,
    bf16* __restrict__ Ch, bf16* __restrict__ Cl,
    int N, int K, int lda, int epi, const int* __restrict__ tok,
    const float* __restrict__ aux0, int bx, int by, int bz) {
    extern __shared__ __align__(16) char raw[];
    const uint32_t sbase = (uint32_t)__cvta_generic_to_shared(raw);

    const int tid = threadIdx.x;
    const int warp = tid >> 5;
    const int wm = warp >> 1, wn = warp & 1;
    const int row0 = by * 64, col0 = bx * 64;
    const int kof = bz * K;

    const int sh = (K == 128) ? 4 : 3;
    const int segsA = 1 << sh;
    for (int i = tid; i < 64 * segsA; i += 128) {
        int r = i >> sh, s = i & (segsA - 1);
        size_t arow = tok ? (size_t)tok[row0 + r] : (size_t)(row0 + r);
        const bf16* ph = Ah + arow * lda + kof + s * 8;
        const bf16* pl = Al + arow * lda + kof + s * 8;
        uint32_t d = sbase + r * (AS2 * 2) + s * 16;
        cpa16(d, ph);
        cpa16(d + 17408, pl);
    }
    for (int i = tid; i < K * 8; i += 128) {
        int r = i >> 3, s = i & 7;
        const bf16* ph = Bh + (size_t)(kof + r) * N + col0 + s * 8;
        const bf16* pl = Bl + (size_t)(kof + r) * N + col0 + s * 8;
        uint32_t d = sbase + 34816 + r * (BS2 * 2) + s * 16;
        cpa16(d, ph);
        cpa16(d + 18432, pl);
    }
    cp_commit();

    wmma::fragment<wmma::accumulator, 16, 16, 16, float> acc[2][2];
#pragma unroll
    for (int i = 0; i < 2; i++)
#pragma unroll
        for (int j = 0; j < 2; j++) wmma::fill_fragment(acc[i][j], 0.f);

    cp_wait0();
    __syncthreads();

    bf16* Ahs = (bf16*)raw;
    bf16* Als = (bf16*)(raw + 17408);
    bf16* Bhs = (bf16*)(raw + 34816);
    bf16* Bls = (bf16*)(raw + 53248);

    for (int kk = 0; kk < K; kk += 16) {
        wmma::fragment<wmma::matrix_a, 16, 16, 16, bf16, wmma::row_major> fah[2], fal[2];
        wmma::fragment<wmma::matrix_b, 16, 16, 16, bf16, wmma::row_major> fbh[2], fbl[2];
#pragma unroll
        for (int mi = 0; mi < 2; mi++) {
            wmma::load_matrix_sync(fah[mi], &Ahs[(wm * 32 + mi * 16) * AS2 + kk], AS2);
            wmma::load_matrix_sync(fal[mi], &Als[(wm * 32 + mi * 16) * AS2 + kk], AS2);
        }
#pragma unroll
        for (int ni = 0; ni < 2; ni++) {
            wmma::load_matrix_sync(fbh[ni], &Bhs[kk * BS2 + wn * 32 + ni * 16], BS2);
            wmma::load_matrix_sync(fbl[ni], &Bls[kk * BS2 + wn * 32 + ni * 16], BS2);
        }
#pragma unroll
        for (int mi = 0; mi < 2; mi++)
#pragma unroll
            for (int ni = 0; ni < 2; ni++) {
                wmma::mma_sync(acc[mi][ni], fah[mi], fbh[ni], acc[mi][ni]);
                wmma::mma_sync(acc[mi][ni], fah[mi], fbl[ni], acc[mi][ni]);
                wmma::mma_sync(acc[mi][ni], fal[mi], fbh[ni], acc[mi][ni]);
            }
    }

    if (epi == 0 || epi == 6) {
        float* dst = C + (epi == 6 ? (size_t)bz * NAA * N : 0);
#pragma unroll
        for (int mi = 0; mi < 2; mi++)
#pragma unroll
            for (int ni = 0; ni < 2; ni++)
                wmma::store_matrix_sync(&dst[(size_t)(row0 + wm * 32 + mi * 16) * N
                                             + col0 + wn * 32 + ni * 16],
                                        acc[mi][ni], N, wmma::mem_row_major);
        return;
    }

    __syncthreads();
    float* Ct = (float*)raw;
#pragma unroll
    for (int mi = 0; mi < 2; mi++)
#pragma unroll
        for (int ni = 0; ni < 2; ni++)
            wmma::store_matrix_sync(&Ct[(wm * 32 + mi * 16) * CS + wn * 32 + ni * 16],
                                    acc[mi][ni], CS, wmma::mem_row_major);
    __syncthreads();

    if (epi == 7) {
#pragma unroll
        for (int it = 0; it < 16; it++) {
            int item = tid + it * 128;
            int r = item >> 5, c = item & 31;
            float v1 = Ct[r * CS + c];
            float v3 = Ct[r * CS + c + 32];
            float hv = (v1 / (1.f + __expf(-v1))) * v3;
            int f = (col0 >> 1) + c;
            size_t o = (size_t)(row0 + r) * 512 + f;
            spl(hv, Ch[o], Cl[o]);
        }
        return;
    }

    if (epi == 8) {
        if (bx < 4) {
            // modulation: qn = (1+g1)*lnq + b1, g1/b1 packed in 32-col pairs
#pragma unroll
            for (int it = 0; it < 16; it++) {
                int item = tid + it * 128;
                int r = item >> 5, c = item & 31;
                float vg = Ct[r * CS + c]      + bias[col0 + c];
                float vb = Ct[r * CS + c + 32] + bias[col0 + c + 32];
                int f = (col0 >> 1) + c;
                size_t o = (size_t)(row0 + r) * DAA + f;
                float qn = (1.f + vg) * aux0[o] + vb;
                spl(qn, Ch[o], Cl[o]);
            }
        } else {
            // g2|b2 -> ad2 (bias added)
#pragma unroll
            for (int it = 0; it < 8; it++) {
                int r = (tid >> 4) + it * 8;
                int c4 = (tid & 15) * 4;
                int gr = row0 + r;
                float4 v4 = *(const float4*)&Ct[r * CS + c4];
                float vv[4] = {v4.x, v4.y, v4.z, v4.w};
#pragma unroll
                for (int u = 0; u < 4; u++) {
                    int gc = col0 + c4 + u;
                    C[(size_t)gr * 256 + (gc - 256)] = vv[u] + bias[gc];
                }
            }
        }
        return;
    }

    // epi == 2
#pragma unroll
    for (int it = 0; it < 8; it++) {
        int r = (tid >> 4) + it * 8;
        int c4 = (tid & 15) * 4;
        int gr = row0 + r;
        float4 v4 = *(const float4*)&Ct[r * CS + c4];
        float vv[4] = {v4.x, v4.y, v4.z, v4.w};
#pragma unroll
        for (int u = 0; u < 4; u++) {
            int gc = col0 + c4 + u;
            float v = vv[u] + bias[gc];
            v = 1.f / (1.f + __expf(-v));
            C[(size_t)gr * N + gc] = v;
        }
    }
}

__global__ __launch_bounds__(128)
void gemm_kernel(const bf16* __restrict__ Ah, const bf16* __restrict__ Al,
                 const bf16* __restrict__ Bh, const bf16* __restrict__ Bl,
                 const float* __restrict__ bias, float* __restrict__ C,
                 bf16* __restrict__ Ch, bf16* __restrict__ Cl,
                 int N, int K, int lda, int epi, const int* __restrict__ tok,
                 const float* __restrict__ aux0) {
    gemm_body(Ah, Al, Bh, Bl, bias, C, Ch, Cl, N, K, lda, epi, tok, aux0,
              blockIdx.x, blockIdx.y, blockIdx.z);
}

// cond (512 CTAs, epi6) + gates (256 CTAs, epi2) fused
__global__ __launch_bounds__(128)
void gemm_cond_gates_kernel(const bf16* __restrict__ hcH, const bf16* __restrict__ hcL,
                            const bf16* __restrict__ WcpH, const bf16* __restrict__ WcpL,
                            float* __restrict__ part, const int* __restrict__ tok,
                            const bf16* __restrict__ caH, const bf16* __restrict__ caL,
                            const bf16* __restrict__ WgH, const bf16* __restrict__ WgL,
                            const float* __restrict__ Bg, float* __restrict__ gates) {
    int b = blockIdx.x;
    if (b < 512) {
        gemm_body(hcH, hcL, WcpH, WcpL, nullptr, part, nullptr, nullptr,
                  DAA, 128, DMM, 6, tok, nullptr, b & 1, (b >> 1) & 63, b >> 7);
    } else {
        int g = b - 512;
        gemm_body(caH, caL, WgH, WgL, Bg, gates, nullptr, nullptr,
                  256, 128, 128, 2, nullptr, nullptr, g & 3, g >> 2, 0);
    }
}

// ---------------- combine kernels ----------------
__global__ void combine3_kernel(const float* __restrict__ part,
                                const float* __restrict__ bias,
                                const float* __restrict__ temb,
                                bf16* __restrict__ outH, bf16* __restrict__ outL) {
    int t = blockIdx.x * blockDim.x + threadIdx.x;
#pragma unroll
    for (int rep = 0; rep < 2; rep++) {
        int idx = (t * 2 + rep) * 4;
        float4 v = *(const float4*)&part[idx];
        float4 p1 = *(const float4*)&part[(size_t)NAA * DAA + idx];
        float4 p2 = *(const float4*)&part[(size_t)2 * NAA * DAA + idx];
        float4 p3 = *(const float4*)&part[(size_t)3 * NAA * DAA + idx];
        int c = idx & 127;
        float4 b = *(const float4*)&bias[c];
        float4 e = *(const float4*)&temb[c];
        float vv[4] = {v.x + p1.x + p2.x + p3.x + b.x + e.x,
                       v.y + p1.y + p2.y + p3.y + b.y + e.y,
                       v.z + p1.z + p2.z + p3.z + b.z + e.z,
                       v.w + p1.w + p2.w + p3.w + b.w + e.w};
        __nv_bfloat162 h2[2], l2[2];
        spl(vv[0], h2[0].x, l2[0].x); spl(vv[1], h2[0].y, l2[0].y);
        spl(vv[2], h2[1].x, l2[1].x); spl(vv[3], h2[1].y, l2[1].y);
        *(uint2*)&outH[idx] = *(uint2*)h2;
        *(uint2*)&outL[idx] = *(uint2*)l2;
    }
}

__global__ __launch_bounds__(256)
void combine4_ln_kernel(const float* __restrict__ part,
                        const float* __restrict__ q, const float* __restrict__ qkvg,
                        const float* __restrict__ gates, const float* __restrict__ ad2,
                        float* __restrict__ q1,
                        bf16* __restrict__ oh, bf16* __restrict__ ol) {
    int row = blockIdx.x * 8 + (threadIdx.x >> 5);
    int lane = threadIdx.x & 31;
    int c0 = lane * 4;
    size_t base = (size_t)row * DAA + c0;
    float4 p0 = *(const float4*)&part[base];
    float4 p1 = *(const float4*)&part[(size_t)NAA * DAA + base];
    float4 qv = *(const float4*)&q[base];
    float4 gv = *(const float4*)&qkvg[(size_t)row * 512 + 384 + c0];
    float4 g1 = *(const float4*)&gates[(size_t)row * 256 + c0];
    float vv[4];
    {
        float pp[4] = {p0.x + p1.x, p0.y + p1.y, p0.z + p1.z, p0.w + p1.w};
        float qq[4] = {qv.x, qv.y, qv.z, qv.w};
        float gg[4] = {gv.x, gv.y, gv.z, gv.w};
        float ga[4] = {g1.x, g1.y, g1.z, g1.w};
#pragma unroll
        for (int u = 0; u < 4; u++) {
            float sg = 1.f / (1.f + __expf(-gg[u]));
            vv[u] = (qq[u] + sg * pp[u]) * (1.f + ga[u]);
        }
    }
    float4 o; o.x = vv[0]; o.y = vv[1]; o.z = vv[2]; o.w = vv[3];
    *(float4*)&q1[base] = o;

    float s = vv[0] + vv[1] + vv[2] + vv[3];
    float sq = vv[0] * vv[0] + vv[1] * vv[1] + vv[2] * vv[2] + vv[3] * vv[3];
#pragma unroll
    for (int off = 16; off; off >>= 1) {
        s  += __shfl_xor_sync(0xffffffffu, s, off);
        sq += __shfl_xor_sync(0xffffffffu, sq, off);
    }
    float m = s * (1.f / 128.f);
    float var = sq * (1.f / 128.f) - m * m;
    float rstd = rsqrtf(var + 1e-5f);
    float4 g2 = *(const float4*)&ad2[(size_t)row * 256 + c0];
    float4 b2 = *(const float4*)&ad2[(size_t)row * 256 + 128 + c0];
    float gg2[4] = {g2.x, g2.y, g2.z, g2.w};
    float bb2[4] = {b2.x, b2.y, b2.z, b2.w};
    __nv_bfloat162 h2[2], l2[2];
#pragma unroll
    for (int u = 0; u < 4; u++) {
        float n = (vv[u] - m) * rstd;
        float r = (1.f + gg2[u]) * n + bb2[u];
        bf16 hh, ll; spl(r, hh, ll);
        ((bf16*)h2)[u] = hh; ((bf16*)l2)[u] = ll;
    }
    *(uint2*)&oh[base] = *(uint2*)h2;
    *(uint2*)&ol[base] = *(uint2*)l2;
}

__global__ void combine5_kernel(const float* __restrict__ part,
                                const float* __restrict__ q1, const float* __restrict__ gates,
                                float* __restrict__ outF) {
    int t = blockIdx.x * blockDim.x + threadIdx.x;
#pragma unroll
    for (int rep = 0; rep < 2; rep++) {
        int idx = (t * 2 + rep) * 4;
        float4 v = *(const float4*)&part[idx];
        float4 p1 = *(const float4*)&part[(size_t)NAA * DAA + idx];
        float4 p2 = *(const float4*)&part[(size_t)2 * NAA * DAA + idx];
        float4 p3 = *(const float4*)&part[(size_t)3 * NAA * DAA + idx];
        float4 qv = *(const float4*)&q1[idx];
        int i = idx >> 7, c = idx & 127;
        float4 g2 = *(const float4*)&gates[(size_t)i * 256 + 128 + c];
        float4 o;
        o.x = qv.x + g2.x * (v.x + p1.x + p2.x + p3.x);
        o.y = qv.y + g2.y * (v.y + p1.y + p2.y + p3.y);
        o.z = qv.z + g2.z * (v.z + p1.z + p2.z + p3.z);
        o.w = qv.w + g2.w * (v.w + p1.w + p2.w + p3.w);
        *(float4*)&outF[idx] = o;
    }
}

// ---------------- prep: weights + activations + scatter, then LN(q) tail blocks ----------------
// elementwise region: 1360256 items -> 5314 blocks (tail padded; scatter bounds-checked)
#define EL_BLOCKS 5314
__global__ void prep_kernel(const float* __restrict__ wq, const float* __restrict__ wk,
                            const float* __restrict__ wv, const float* __restrict__ wg,
                            const float* __restrict__ ad1w, const float* __restrict__ ad2w,
                            const float* __restrict__ sw1, const float* __restrict__ sw3,
                            const float* __restrict__ g1w, const float* __restrict__ g2w,
                            const float* __restrict__ cpw, const float* __restrict__ wo,
                            const float* __restrict__ sw2, const float* __restrict__ c_atom,
                            const float* __restrict__ h_cond,
                            const float* __restrict__ ad1b, const float* __restrict__ ad2b,
                            const float* __restrict__ g1b, const float* __restrict__ g2b,
                            const int* __restrict__ p_lm_idx,
                            const float* __restrict__ q, const float* __restrict__ lng,
                            const float* __restrict__ lnb, float* __restrict__ lnq) {
    if (blockIdx.x >= EL_BLOCKS) {
        // LN(q) tail: warp per row
        int row = (blockIdx.x - EL_BLOCKS) * 8 + (threadIdx.x >> 5);
        int lane = threadIdx.x & 31;
        const float* xr = q + (size_t)row * DAA;
        float4 v = *(const float4*)(xr + lane * 4);
        float s = v.x + v.y + v.z + v.w;
        float sq = v.x * v.x + v.y * v.y + v.z * v.z + v.w * v.w;
#pragma unroll
        for (int o = 16; o; o >>= 1) {
            s  += __shfl_xor_sync(0xffffffffu, s, o);
            sq += __shfl_xor_sync(0xffffffffu, sq, o);
        }
        float m = s * (1.f / 128.f);
        float var = sq * (1.f / 128.f) - m * m;
        float rstd = rsqrtf(var + 1e-5f);
        float xv[4] = {v.x, v.y, v.z, v.w};
        float4 o4;
        float* po = (float*)&o4;
#pragma unroll
        for (int u = 0; u < 4; u++) {
            int c = lane * 4 + u;
            po[u] = ((xv[u] - m) * rstd) * lng[c] + lnb[c];
        }
        *(float4*)&lnq[(size_t)row * DAA + lane * 4] = o4;
        return;
    }
    int idx = blockIdx.x * blockDim.x + threadIdx.x;
    if (idx < 16384) {
        int r = idx >> 7, c = idx & 127;
        size_t o = (size_t)r * 512;
        spl(wq[idx], d_Wqkvg_h[o + c],       d_Wqkvg_l[o + c]);
        spl(wk[idx], d_Wqkvg_h[o + 128 + c], d_Wqkvg_l[o + 128 + c]);
        spl(wv[idx], d_Wqkvg_h[o + 256 + c], d_Wqkvg_l[o + 256 + c]);
        spl(wg[idx], d_Wqkvg_h[o + 384 + c], d_Wqkvg_l[o + 384 + c]);
        return;
    }
    idx -= 16384;
    if (idx < 32768) {
        int r = idx >> 8, c = idx & 255;
        size_t o = (size_t)r * 512;
        // adaln1: pack g1/b1 interleaved in 32-col groups
        int p;
        if (c < 128) p = (c >> 5) * 64 + (c & 31);
        else { int cb = c - 128; p = (cb >> 5) * 64 + 32 + (cb & 31); }
        spl(ad1w[idx], d_Wad_h[o + p], d_Wad_l[o + p]);
        spl(ad2w[idx], d_Wad_h[o + 256 + c], d_Wad_l[o + 256 + c]);
        return;
    }
    idx -= 32768;
    if (idx < 65536) {
        int k = idx >> 9, f = idx & 511;
        int g = f >> 5, w = f & 31;
        size_t o = (size_t)k * 1024;
        spl(sw1[idx], d_Wff_h[o + g * 64 + w],      d_Wff_l[o + g * 64 + w]);
        spl(sw3[idx], d_Wff_h[o + g * 64 + 32 + w], d_Wff_l[o + g * 64 + 32 + w]);
        return;
    }
    idx -= 65536;
    if (idx < 16384) {
        int r = idx >> 7, c = idx & 127;
        size_t o = (size_t)r * 256;
        spl(g1w[idx], d_Wg_h[o + c],       d_Wg_l[o + c]);
        spl(g2w[idx], d_Wg_h[o + 128 + c], d_Wg_l[o + 128 + c]);
        return;
    }
    idx -= 16384;
    if (idx < 65536) { spl(cpw[idx], d_Wcp_h[idx], d_Wcp_l[idx]); return; }
    idx -= 65536;
    if (idx < 16384) { spl(wo[idx], d_Wo_h[idx], d_Wo_l[idx]); return; }
    idx -= 16384;
    if (idx < 65536) { spl(sw2[idx], d_Ws2_h[idx], d_Ws2_l[idx]); return; }
    idx -= 65536;
    if (idx < 524288) { spl(c_atom[idx], d_ca_h[idx], d_ca_l[idx]); return; }
    idx -= 524288;
    if (idx < 524288) { spl(h_cond[idx], d_hc_h[idx], d_hc_l[idx]); return; }
    idx -= 524288;
    if (idx < 256) {
        int c = idx;
        int p;
        if (c < 128) p = (c >> 5) * 64 + (c & 31);
        else { int cb = c - 128; p = (cb >> 5) * 64 + 32 + (cb & 31); }
        d_Bad[p] = ad1b[c];
        d_Bad[256 + c] = ad2b[c];
        return;
    }
    idx -= 256;
    if (idx < 128) { d_Bg[idx] = g1b[idx]; d_Bg[128 + idx] = g2b[idx]; return; }
    idx -= 128;
    if (idx < PPP) {
        int i = p_lm_idx[2 * idx], j = p_lm_idx[2 * idx + 1];
        int dlt = j - i;
        if (dlt >= -WIN && dlt <= WIN) atomicMax(&d_bandp[i * BAND + dlt + WIN], idx + 1);
    }
}

// ---------------- banded attention, 8 queries per CTA ----------------
#define QB 8
#define KROWS 40

__global__ __launch_bounds__(256)
void attn_kernel(const float* __restrict__ QKVG, const int* __restrict__ bp,
                 const float* __restrict__ p_lm, const float* __restrict__ pair_w,
                 const float* __restrict__ pair_b,
                 bf16* __restrict__ oh, bf16* __restrict__ ol) {
    __shared__ float Kb[KROWS][DAA];
    __shared__ float Vb[KROWS][DAA];
    __shared__ float Qv[QB][DAA];
    __shared__ float sc[QB][4][BAND];
    const int i0 = blockIdx.x * QB;
    const int tid = threadIdx.x;
    const int jlo = (i0 - WIN) > 0 ? (i0 - WIN) : 0;
    const int jhi = (i0 + QB - 1 + WIN) < (NAA - 1) ? (i0 + QB - 1 + WIN) : (NAA - 1);
    const int rows = jhi - jlo + 1;

    for (int idx = tid; idx < QB * DAA; idx += 256) {
        int qq = idx >> 7, c = idx & 127;
        Qv[qq][c] = QKVG[(size_t)(i0 + qq) * 512 + c];
    }
    for (int idx = tid; idx < rows * DAA; idx += 256) {
        int r = idx >> 7, c = idx & 127;
        const float* src = QKVG + (size_t)(jlo + r) * 512;
        Kb[r][c] = src[128 + c];
        Vb[r][c] = src[256 + c];
    }
    __syncthreads();

    for (int s = tid; s < QB * 4 * BAND; s += 256) {
        int qq = s / (4 * BAND);
        int r2 = s - qq * (4 * BAND);
        int h = r2 & 3, jj = r2 >> 2;
        int i = i0 + qq;
        int j = i - WIN + jj;
        float acc = -INFINITY;
        if (j >= 0 && j < NAA) {
            int kr = j - jlo;
            acc = 0.f;
#pragma unroll
            for (int d = 0; d < 32; d++) acc += Qv[qq][h * 32 + d] * Kb[kr][h * 32 + d];
            acc *= 0.17677669529663687f;
            int p = bp[i * BAND + jj];
            if (p > 0) {
                p -= 1;
                float bs = pair_b[h];
#pragma unroll
                for (int t = 0; t < 16; t++) bs += p_lm[p * 16 + t] * pair_w[t * 4 + h];
                acc += bs;
            }
        }
        sc[qq][h][jj] = acc;
    }
    __syncthreads();

    {
        int w = tid >> 5, lane = tid & 31;
#pragma unroll
        for (int rep = 0; rep < 4; rep++) {
            int pair = w * 4 + rep;            // 32 (q,h) pairs
            int qq = pair >> 2, h = pair & 3;
            float v0 = sc[qq][h][lane];
            float v1 = (lane == 0) ? sc[qq][h][32] : -INFINITY;
            float mx = fmaxf(v0, v1);
#pragma unroll
            for (int o = 16; o; o >>= 1) mx = fmaxf(mx, __shfl_xor_sync(0xffffffffu, mx, o));
            float e0 = __expf(v0 - mx);
            float e1 = (lane == 0) ? __expf(v1 - mx) : 0.f;
            float sm = e0 + e1;
#pragma unroll
            for (int o = 16; o; o >>= 1) sm += __shfl_xor_sync(0xffffffffu, sm, o);
            float inv = 1.f / sm;
            sc[qq][h][lane] = e0 * inv;
            if (lane == 0) sc[qq][h][32] = e1 * inv;
        }
    }
    __syncthreads();

    for (int idx = tid; idx < QB * DAA; idx += 256) {
        int qq = idx >> 7, col = idx & 127;
        int h = col >> 5;
        int i = i0 + qq;
        float o = 0.f;
#pragma unroll
        for (int jj = 0; jj < BAND; jj++) {
            int j = i - WIN + jj;
            if (j >= 0 && j < NAA)
                o += sc[qq][h][jj] * Vb[j - jlo][col];
        }
        spl(o, oh[(size_t)i * DAA + col], ol[(size_t)i * DAA + col]);
    }
}

// ---------------- launch ----------------
extern "C" void kernel_launch(void* const* d_in, const int* in_sizes, int n_in,
                              void* d_out, int out_size) {
    const float* q           = (const float*)d_in[0];
    const float* c_atom      = (const float*)d_in[1];
    const float* h_cond      = (const float*)d_in[2];
    const float* p_lm        = (const float*)d_in[3];
    const float* t_emb       = (const float*)d_in[4];
    const float* cond_proj_w = (const float*)d_in[5];
    const float* cond_proj_b = (const float*)d_in[6];
    const float* adaln1_w    = (const float*)d_in[7];
    const float* adaln1_b    = (const float*)d_in[8];
    const float* adaln2_w    = (const float*)d_in[9];
    const float* adaln2_b    = (const float*)d_in[10];
    const float* ln_g        = (const float*)d_in[11];
    const float* ln_b        = (const float*)d_in[12];
    const float* wq          = (const float*)d_in[13];
    const float* wk          = (const float*)d_in[14];
    const float* wv          = (const float*)d_in[15];
    const float* wg          = (const float*)d_in[16];
    const float* wo          = (const float*)d_in[17];
    const float* pair_w      = (const float*)d_in[18];
    const float* pair_b      = (const float*)d_in[19];
    const float* gate1_w     = (const float*)d_in[20];
    const float* gate1_b     = (const float*)d_in[21];
    const float* gate2_w     = (const float*)d_in[22];
    const float* gate2_b     = (const float*)d_in[23];
    const float* sw1         = (const float*)d_in[24];
    const float* sw3         = (const float*)d_in[25];
    const float* sw2         = (const float*)d_in[26];
    const int*   p_lm_idx    = (const int*)d_in[27];
    const int*   token_idx   = (const int*)d_in[28];
    float* out = (float*)d_out;

#define SYM(T, p, s) T* p; cudaGetSymbolAddress((void**)&p, s)
    SYM(float, ad2, d_ad2); SYM(float, qkvg, d_qkvg); SYM(float, gates, d_gates);
    SYM(float, q1, d_q1); SYM(float, lnq, d_lnq); SYM(int, bandp, d_bandp);
    SYM(float, part, d_part);
    SYM(float, Bad, d_Bad); SYM(float, Bg, d_Bg);
    SYM(bf16, cond_h, d_cond_h); SYM(bf16, cond_l, d_cond_l);
    SYM(bf16, qn_h, d_qn_h); SYM(bf16, qn_l, d_qn_l);
    SYM(bf16, qn2_h, d_qn2_h); SYM(bf16, qn2_l, d_qn2_l);
    SYM(bf16, at_h, d_at_h); SYM(bf16, at_l, d_at_l);
    SYM(bf16, hid_h, d_hid_h); SYM(bf16, hid_l, d_hid_l);
    SYM(bf16, ca_h, d_ca_h); SYM(bf16, ca_l, d_ca_l);
    SYM(bf16, hc_h, d_hc_h); SYM(bf16, hc_l, d_hc_l);
    SYM(bf16, Wqkvg_h, d_Wqkvg_h); SYM(bf16, Wqkvg_l, d_Wqkvg_l);
    SYM(bf16, Wad_h, d_Wad_h); SYM(bf16, Wad_l, d_Wad_l);
    SYM(bf16, Wff_h, d_Wff_h); SYM(bf16, Wff_l, d_Wff_l);
    SYM(bf16, Wg_h, d_Wg_h); SYM(bf16, Wg_l, d_Wg_l);
    SYM(bf16, Wcp_h, d_Wcp_h); SYM(bf16, Wcp_l, d_Wcp_l);
    SYM(bf16, Wo_h, d_Wo_h); SYM(bf16, Wo_l, d_Wo_l);
    SYM(bf16, Ws2_h, d_Ws2_h); SYM(bf16, Ws2_l, d_Ws2_l);
#undef SYM

    cudaFuncSetAttribute(gemm_kernel, cudaFuncAttributeMaxDynamicSharedMemorySize, GSM);
    cudaFuncSetAttribute(gemm_cond_gates_kernel, cudaFuncAttributeMaxDynamicSharedMemorySize, GSM);

    // prep (elementwise + scatter) + LN(q) tail (512 blocks)
    prep_kernel<<<EL_BLOCKS + 512, 256>>>(wq, wk, wv, wg, adaln1_w, adaln2_w,
                                          sw1, sw3, gate1_w, gate2_w,
                                          cond_proj_w, wo, sw2, c_atom, h_cond,
                                          adaln1_b, adaln2_b, gate1_b, gate2_b,
                                          p_lm_idx, q, ln_g, ln_b, lnq);

    // cond split-K x4 + gates fused
    gemm_cond_gates_kernel<<<768, 128, GSM>>>(hc_h, hc_l, Wcp_h, Wcp_l, part, token_idx,
                                              ca_h, ca_l, Wg_h, Wg_l, Bg, gates);
    combine3_kernel<<<256, 256>>>(part, cond_proj_b, t_emb, cond_h, cond_l);
    // adaln combined (epi=8): bx<4 modulation -> qn hi/lo; bx>=4 -> ad2
    gemm_kernel<<<dim3(8, 64), 128, GSM>>>(cond_h, cond_l, Wad_h, Wad_l, Bad,
                                           ad2, qn_h, qn_l, 512, 128, 128, 8,
                                           nullptr, lnq);
    // QKVG
    gemm_kernel<<<dim3(8, 64), 128, GSM>>>(qn_h, qn_l, Wqkvg_h, Wqkvg_l, nullptr,
                                           qkvg, nullptr, nullptr, 512, 128, 128, 0,
                                           nullptr, nullptr);
    // attention (8 queries per CTA)
    attn_kernel<<<NAA / QB, 256>>>(qkvg, bandp, p_lm, pair_w, pair_b, at_h, at_l);
    // wo split-K x2 -> combine4+LN (reads ad2)
    gemm_kernel<<<dim3(2, 64, 2), 128, GSM>>>(at_h, at_l, Wo_h, Wo_l, nullptr,
                                              part, nullptr, nullptr, DAA, 64, DAA, 6,
                                              nullptr, nullptr);
    combine4_ln_kernel<<<512, 256>>>(part, q, qkvg, gates, ad2, q1, qn2_h, qn2_l);
    // FF with fused swiglu (epi=7)
    gemm_kernel<<<dim3(16, 64), 128, GSM>>>(qn2_h, qn2_l, Wff_h, Wff_l, nullptr,
                                            nullptr, hid_h, hid_l, 1024, 128, 128, 7,
                                            nullptr, nullptr);
    // sw2 split-K x4 -> combine5
    gemm_kernel<<<dim3(2, 64, 4), 128, GSM>>>(hid_h, hid_l, Ws2_h, Ws2_l, nullptr,
                                              part, nullptr, nullptr, DAA, 128, DMM, 6,
                                              nullptr, nullptr);
    combine5_kernel<<<256, 256>>>(part, q1, gates, out);
}